// round 4
// baseline (speedup 1.0000x reference)
#include <cuda_runtime.h>
#include <cuda_bf16.h>
#include <math.h>

// Problem constants
constexpr int Bsz = 4;
constexpr int L   = 4096;
constexpr int D   = 1024;
constexpr int H   = 16;
constexpr int G   = 8;
constexpr int LG  = L / G;     // 512
constexpr int DH  = D / H;     // 64
constexpr int M_TOK = Bsz * L; // 16384

// Scratch (allocation-free: static __device__ globals)
__device__ float g_qkv[(size_t)M_TOK * 3 * D];   // [B*L, 3D]
__device__ float g_att[(size_t)M_TOK * D];       // [B*L, D]

// ---------------------------------------------------------------------------
// SGEMM: C[M,N] = A[M,K] * B[N,K]^T (+ bias[n]), all row-major fp32.
// 128x128 tile, BK=16, 256 threads, 8x8 micro-tile.
// Assumes M%128==0, N%128==0, K%16==0 (true for all our shapes).
// ---------------------------------------------------------------------------
__global__ __launch_bounds__(256) void sgemm_nt(const float* __restrict__ A,
                                                const float* __restrict__ B,
                                                const float* __restrict__ bias,
                                                float* __restrict__ C,
                                                int M, int N, int K)
{
    __shared__ float As[16][128];
    __shared__ float Bs[16][128];

    const int tid = threadIdx.x;
    const int bm = blockIdx.y * 128;
    const int bn = blockIdx.x * 128;

    const int lrow = tid >> 2;          // 0..63 (load rows lrow, lrow+64)
    const int lc4  = (tid & 3) * 4;     // 0,4,8,12
    const int trow = (tid >> 4) * 8;    // compute rows
    const int tcol = (tid & 15) * 8;    // compute cols

    const float* Ap = A + (size_t)(bm + lrow) * K + lc4;
    const float* Bp = B + (size_t)(bn + lrow) * K + lc4;

    float acc[8][8];
    #pragma unroll
    for (int i = 0; i < 8; i++)
        #pragma unroll
        for (int j = 0; j < 8; j++) acc[i][j] = 0.f;

    for (int k0 = 0; k0 < K; k0 += 16) {
        #pragma unroll
        for (int r = 0; r < 2; r++) {
            float4 a = *(const float4*)(Ap + (size_t)r * 64 * K + k0);
            As[lc4 + 0][lrow + r * 64] = a.x;
            As[lc4 + 1][lrow + r * 64] = a.y;
            As[lc4 + 2][lrow + r * 64] = a.z;
            As[lc4 + 3][lrow + r * 64] = a.w;
            float4 b = *(const float4*)(Bp + (size_t)r * 64 * K + k0);
            Bs[lc4 + 0][lrow + r * 64] = b.x;
            Bs[lc4 + 1][lrow + r * 64] = b.y;
            Bs[lc4 + 2][lrow + r * 64] = b.z;
            Bs[lc4 + 3][lrow + r * 64] = b.w;
        }
        __syncthreads();

        #pragma unroll
        for (int k = 0; k < 16; k++) {
            float a[8], b[8];
            *(float4*)&a[0] = *(const float4*)&As[k][trow];
            *(float4*)&a[4] = *(const float4*)&As[k][trow + 4];
            *(float4*)&b[0] = *(const float4*)&Bs[k][tcol];
            *(float4*)&b[4] = *(const float4*)&Bs[k][tcol + 4];
            #pragma unroll
            for (int i = 0; i < 8; i++)
                #pragma unroll
                for (int j = 0; j < 8; j++)
                    acc[i][j] = fmaf(a[i], b[j], acc[i][j]);
        }
        __syncthreads();
    }

    #pragma unroll
    for (int i = 0; i < 8; i++) {
        const size_t row = (size_t)(bm + trow + i) * N + bn + tcol;
        #pragma unroll
        for (int j = 0; j < 8; j += 4) {
            float4 v;
            v.x = acc[i][j + 0];
            v.y = acc[i][j + 1];
            v.z = acc[i][j + 2];
            v.w = acc[i][j + 3];
            if (bias) {
                v.x += bias[bn + tcol + j + 0];
                v.y += bias[bn + tcol + j + 1];
                v.z += bias[bn + tcol + j + 2];
                v.w += bias[bn + tcol + j + 3];
            }
            *(float4*)&C[row + j] = v;
        }
    }
}

// ---------------------------------------------------------------------------
// Blocked attention. One CTA = one (b,h,g) block x 32-query tile.
// Full 32x512 score rows in smem; no online softmax needed.
// grid.x = B*H*G*16 = 8192, 256 threads.
// ---------------------------------------------------------------------------
constexpr int S_LD  = 513;   // padded row stride for S
constexpr int Q_LD  = 65;
constexpr int KV_LD = 65;
constexpr int ATTN_SMEM = (32 * S_LD + 32 * Q_LD + 64 * KV_LD) * 4;  // 90624 B

__global__ __launch_bounds__(256) void attn_kernel(const float* __restrict__ qkv,
                                                   float* __restrict__ att)
{
    extern __shared__ float sm[];
    float* S   = sm;                    // [32][513]
    float* Qs  = S + 32 * S_LD;         // [32][65]
    float* KVs = Qs + 32 * Q_LD;        // [64][65]

    const int tid = threadIdx.x;
    const int idx = blockIdx.x;
    const int qt  = idx & 15;           // q-tile within block
    const int bhg = idx >> 4;
    const int g = bhg & 7;
    const int h = (bhg >> 3) & 15;
    const int b = bhg >> 7;

    const int pos0  = g * LG;
    const int qpos0 = pos0 + qt * 32;
    const float scale = 0.125f;         // 64^-0.5

    const float* qbase = qkv + ((size_t)(b * L + qpos0) * (3 * D)) + h * DH;
    const float* kbase = qkv + ((size_t)(b * L + pos0)  * (3 * D)) + D + h * DH;
    const float* vbase = kbase + D;

    // Load Q tile: 32 rows x 64 -> 512 float4 -> 2 per thread
    #pragma unroll
    for (int i = 0; i < 2; i++) {
        int f = tid + i * 256;
        int row = f >> 4;
        int c4 = (f & 15) * 4;
        float4 v = *(const float4*)(qbase + (size_t)row * (3 * D) + c4);
        float* dst = Qs + row * Q_LD + c4;
        dst[0] = v.x; dst[1] = v.y; dst[2] = v.z; dst[3] = v.w;
    }

    // Micro-tile mapping: 4 rows x 2 cols per thread
    const int lane = tid & 31;
    const int wid  = tid >> 5;
    const int r0 = wid * 4;             // rows r0..r0+3
    const int c0 = lane * 2;            // cols c0, c0+1

    // ---- Pass 1: S = scale * Q K^T ----
    for (int ck = 0; ck < 8; ck++) {
        __syncthreads();
        #pragma unroll
        for (int i = 0; i < 4; i++) {
            int f = tid + i * 256;
            int row = f >> 4;
            int c4 = (f & 15) * 4;
            float4 v = *(const float4*)(kbase + (size_t)(ck * 64 + row) * (3 * D) + c4);
            float* dst = KVs + row * KV_LD + c4;
            dst[0] = v.x; dst[1] = v.y; dst[2] = v.z; dst[3] = v.w;
        }
        __syncthreads();

        float acc[4][2] = {};
        #pragma unroll
        for (int d = 0; d < 64; d++) {
            float k0 = KVs[c0 * KV_LD + d];
            float k1 = KVs[(c0 + 1) * KV_LD + d];
            #pragma unroll
            for (int i = 0; i < 4; i++) {
                float q = Qs[(r0 + i) * Q_LD + d];
                acc[i][0] = fmaf(q, k0, acc[i][0]);
                acc[i][1] = fmaf(q, k1, acc[i][1]);
            }
        }
        #pragma unroll
        for (int i = 0; i < 4; i++) {
            S[(r0 + i) * S_LD + ck * 64 + c0]     = acc[i][0] * scale;
            S[(r0 + i) * S_LD + ck * 64 + c0 + 1] = acc[i][1] * scale;
        }
    }
    __syncthreads();

    // ---- Pass 2: row softmax (warp w handles rows 4w..4w+3) ----
    for (int r = wid * 4; r < wid * 4 + 4; r++) {
        float* row = S + r * S_LD;
        float m = -INFINITY;
        for (int j = lane; j < 512; j += 32) m = fmaxf(m, row[j]);
        #pragma unroll
        for (int o = 16; o; o >>= 1) m = fmaxf(m, __shfl_xor_sync(0xffffffffu, m, o));
        float s = 0.f;
        for (int j = lane; j < 512; j += 32) {
            float e = __expf(row[j] - m);
            row[j] = e;
            s += e;
        }
        #pragma unroll
        for (int o = 16; o; o >>= 1) s += __shfl_xor_sync(0xffffffffu, s, o);
        float inv = 1.0f / s;
        for (int j = lane; j < 512; j += 32) row[j] *= inv;
    }
    __syncthreads();

    // ---- Pass 3: O = P V ----
    float oacc[4][2] = {};
    for (int ck = 0; ck < 8; ck++) {
        __syncthreads();
        #pragma unroll
        for (int i = 0; i < 4; i++) {
            int f = tid + i * 256;
            int row = f >> 4;
            int c4 = (f & 15) * 4;
            float4 v = *(const float4*)(vbase + (size_t)(ck * 64 + row) * (3 * D) + c4);
            float* dst = KVs + row * KV_LD + c4;
            dst[0] = v.x; dst[1] = v.y; dst[2] = v.z; dst[3] = v.w;
        }
        __syncthreads();

        #pragma unroll
        for (int kk = 0; kk < 64; kk++) {
            float v0 = KVs[kk * KV_LD + c0];
            float v1 = KVs[kk * KV_LD + c0 + 1];
            #pragma unroll
            for (int i = 0; i < 4; i++) {
                float p = S[(r0 + i) * S_LD + ck * 64 + kk];
                oacc[i][0] = fmaf(p, v0, oacc[i][0]);
                oacc[i][1] = fmaf(p, v1, oacc[i][1]);
            }
        }
    }

    #pragma unroll
    for (int i = 0; i < 4; i++) {
        float* dst = att + ((size_t)(b * L + qpos0 + r0 + i) * D) + h * DH + c0;
        dst[0] = oacc[i][0];
        dst[1] = oacc[i][1];
    }
}

// ---------------------------------------------------------------------------
extern "C" void kernel_launch(void* const* d_in, const int* in_sizes, int n_in,
                              void* d_out, int out_size)
{
    const float* x     = (const float*)d_in[0];   // [B,L,D]
    const float* w_qkv = (const float*)d_in[1];   // [3D, D]
    const float* w_out = (const float*)d_in[2];   // [D, D]
    const float* b_out = (const float*)d_in[3];   // [D]
    float* out = (float*)d_out;                   // [B,L,D]

    float* qkv_ptr = nullptr;
    float* att_ptr = nullptr;
    cudaGetSymbolAddress((void**)&qkv_ptr, g_qkv);
    cudaGetSymbolAddress((void**)&att_ptr, g_att);

    cudaFuncSetAttribute(attn_kernel, cudaFuncAttributeMaxDynamicSharedMemorySize,
                         ATTN_SMEM);

    dim3 blk(256);
    // 1) QKV projection: [16384,1024] x [3072,1024]^T -> [16384,3072]
    sgemm_nt<<<dim3(3 * D / 128, M_TOK / 128), blk>>>(x, w_qkv, nullptr, qkv_ptr,
                                                      M_TOK, 3 * D, D);
    // 2) Blocked attention
    attn_kernel<<<Bsz * H * G * 16, blk, ATTN_SMEM>>>(qkv_ptr, att_ptr);
    // 3) Output projection + bias: [16384,1024] x [1024,1024]^T -> out
    sgemm_nt<<<dim3(D / 128, M_TOK / 128), blk>>>(att_ptr, w_out, b_out, out,
                                                  M_TOK, D, D);
}

// round 6
// speedup vs baseline: 1.8508x; 1.8508x over previous
#include <cuda_runtime.h>
#include <cuda_bf16.h>
#include <math.h>
#include <stdint.h>

// Problem constants
constexpr int Bsz = 4;
constexpr int L   = 4096;
constexpr int D   = 1024;
constexpr int H   = 16;
constexpr int G   = 8;
constexpr int LG  = L / G;     // 512
constexpr int DH  = D / H;     // 64
constexpr int M_TOK = Bsz * L; // 16384
constexpr int KSPLIT = 3 * D;  // 3072 : [hi | lo | hi] x [hi | hi | lo]

// Scratch (allocation-free: static __device__ globals)
__device__ float g_qkv[(size_t)M_TOK * 3 * D];            // [B*L, 3D] fp32
__device__ float g_att[(size_t)M_TOK * D];                // [B*L, D]  fp32
__device__ __nv_bfloat16 g_x2  [(size_t)M_TOK * KSPLIT];  // [16384, 3072]
__device__ __nv_bfloat16 g_att2[(size_t)M_TOK * KSPLIT];  // [16384, 3072]
__device__ __nv_bfloat16 g_wq2 [(size_t)(3 * D) * KSPLIT];// [3072, 3072]
__device__ __nv_bfloat16 g_wo2 [(size_t)D * KSPLIT];      // [1024, 3072]

// ---------------------------------------------------------------------------
// Split fp32 [rows,1024] -> bf16 [rows,3072].
// mode 0 (A side): [hi | lo | hi]     mode 1 (B side): [hi | hi | lo]
// ---------------------------------------------------------------------------
__global__ void split_fp32_bf16x2(const float* __restrict__ src,
                                  __nv_bfloat16* __restrict__ dst,
                                  int rows, int mode)
{
    int idx = blockIdx.x * 256 + threadIdx.x;
    if (idx >= rows * 256) return;
    int row = idx >> 8;
    int c4  = (idx & 255) << 2;
    float4 v = *(const float4*)(src + (size_t)row * 1024 + c4);
    float vv[4] = {v.x, v.y, v.z, v.w};
    __align__(8) __nv_bfloat16 h[4];
    __align__(8) __nv_bfloat16 l[4];
    #pragma unroll
    for (int j = 0; j < 4; j++) {
        h[j] = __float2bfloat16(vv[j]);
        l[j] = __float2bfloat16(vv[j] - __bfloat162float(h[j]));
    }
    uint2 hp = *reinterpret_cast<uint2*>(h);
    uint2 lp = *reinterpret_cast<uint2*>(l);
    __nv_bfloat16* base = dst + (size_t)row * KSPLIT + c4;
    if (mode == 0) {
        *reinterpret_cast<uint2*>(base)        = hp;
        *reinterpret_cast<uint2*>(base + 1024) = lp;
        *reinterpret_cast<uint2*>(base + 2048) = hp;
    } else {
        *reinterpret_cast<uint2*>(base)        = hp;
        *reinterpret_cast<uint2*>(base + 1024) = hp;
        *reinterpret_cast<uint2*>(base + 2048) = lp;
    }
}

// ---------------------------------------------------------------------------
// mma.sync bf16 NT GEMM: C[M,N] = A[M,K]*B[N,K]^T (+bias), fp32 accum.
// Tile 128x128, BK=64 bf16 (128B SW128-swizzled smem rows), 256 threads,
// 8 warps (4x2), warp tile 32x64, 3-stage cp.async pipeline.
// Requires M%128==0, N%128==0, K%64==0.
// ---------------------------------------------------------------------------
__device__ __forceinline__ uint32_t swz(uint32_t off) {
    return off ^ ((off >> 3) & 0x70);
}
__device__ __forceinline__ uint32_t s2u(const void* p) {
    uint32_t a;
    asm("{ .reg .u64 t; cvta.to.shared.u64 t, %1; cvt.u32.u64 %0, t; }"
        : "=r"(a) : "l"(p));
    return a;
}

constexpr int TILE_BYTES = 128 * 128;        // 16KB per operand tile
constexpr int STAGE_BYTES = 2 * TILE_BYTES;  // A + B
constexpr int GEMM_SMEM = 3 * STAGE_BYTES;   // 96KB, 3 stages

__global__ __launch_bounds__(256) void gemm_mma(const __nv_bfloat16* __restrict__ A,
                                                const __nv_bfloat16* __restrict__ B,
                                                const float* __restrict__ bias,
                                                float* __restrict__ C,
                                                int M, int N, int Kt)
{
    extern __shared__ __align__(1024) uint8_t smem[];

    const int tid  = threadIdx.x;
    const int wid  = tid >> 5;
    const int lane = tid & 31;
    const int warp_m = (wid & 3) * 32;   // 0,32,64,96
    const int warp_n = (wid >> 2) * 64;  // 0,64
    const size_t bm = (size_t)blockIdx.y * 128;
    const size_t bn = (size_t)blockIdx.x * 128;
    const uint32_t sbase = s2u(smem);

    // ---- copy mapping: 1024 x 16B per tile, 4 per thread ----
    uint32_t soff[4];
    const __nv_bfloat16 *ag[4], *bg[4];
    #pragma unroll
    for (int i = 0; i < 4; i++) {
        int f = tid + i * 256;
        int row = f >> 3;
        int seg = f & 7;
        soff[i] = swz(row * 128 + seg * 16);
        ag[i] = A + (bm + row) * (size_t)Kt + seg * 8;
        bg[i] = B + (bn + row) * (size_t)Kt + seg * 8;
    }

    const int NC = Kt / 64;

    auto issue_copy = [&](int c, int stage) {
        uint32_t sa = sbase + stage * STAGE_BYTES;
        uint32_t sb = sa + TILE_BYTES;
        const int ko = c * 64;
        #pragma unroll
        for (int i = 0; i < 4; i++) {
            asm volatile("cp.async.cg.shared.global [%0], [%1], 16;"
                         :: "r"(sa + soff[i]), "l"(ag[i] + ko));
            asm volatile("cp.async.cg.shared.global [%0], [%1], 16;"
                         :: "r"(sb + soff[i]), "l"(bg[i] + ko));
        }
        asm volatile("cp.async.commit_group;");
    };

    // ---- ldmatrix source addresses (per-thread, per stage-invariant part) ----
    // A x4: lanes0-7 rows0-7 chunk0 | 8-15 rows8-15 chunk0 | 16-23 rows0-7 chunk1 | 24-31 rows8-15 chunk1
    const int a_row = warp_m + (lane & 15);          // + mt*16
    const int a_sub = lane >> 4;                     // 16B half within k16
    // B x4: row = j*16 + ((lane>>4)&1)*8 + (lane&7); chunk = (lane>>3)&1
    const int b_row = warp_n + ((lane >> 4) & 1) * 8 + (lane & 7);  // + j*16
    const int b_sub = (lane >> 3) & 1;

    float acc[2][8][4];
    #pragma unroll
    for (int mt = 0; mt < 2; mt++)
        #pragma unroll
        for (int nt = 0; nt < 8; nt++)
            #pragma unroll
            for (int q = 0; q < 4; q++) acc[mt][nt][q] = 0.f;

    // ---- prologue: stages 0,1 ----
    issue_copy(0, 0);
    if (NC > 1) issue_copy(1, 1);

    for (int c = 0; c < NC; c++) {
        if (c + 2 < NC) {
            issue_copy(c + 2, (c + 2) % 3);
            asm volatile("cp.async.wait_group 2;");
        } else if (c + 1 < NC) {
            asm volatile("cp.async.wait_group 1;");
        } else {
            asm volatile("cp.async.wait_group 0;");
        }
        __syncthreads();

        const uint32_t sa = sbase + (c % 3) * STAGE_BYTES;
        const uint32_t sb = sa + TILE_BYTES;

        #pragma unroll
        for (int kk = 0; kk < 4; kk++) {
            uint32_t af[2][4];
            #pragma unroll
            for (int mt = 0; mt < 2; mt++) {
                uint32_t off = (uint32_t)(a_row + mt * 16) * 128 + kk * 32 + a_sub * 16;
                asm volatile("ldmatrix.sync.aligned.m8n8.x4.shared.b16 {%0,%1,%2,%3}, [%4];"
                             : "=r"(af[mt][0]), "=r"(af[mt][1]), "=r"(af[mt][2]), "=r"(af[mt][3])
                             : "r"(sa + swz(off)));
            }
            uint32_t bf[8][2];
            #pragma unroll
            for (int j = 0; j < 4; j++) {
                uint32_t off = (uint32_t)(b_row + j * 16) * 128 + kk * 32 + b_sub * 16;
                uint32_t r0, r1, r2, r3;
                asm volatile("ldmatrix.sync.aligned.m8n8.x4.shared.b16 {%0,%1,%2,%3}, [%4];"
                             : "=r"(r0), "=r"(r1), "=r"(r2), "=r"(r3)
                             : "r"(sb + swz(off)));
                bf[2 * j][0] = r0; bf[2 * j][1] = r1;
                bf[2 * j + 1][0] = r2; bf[2 * j + 1][1] = r3;
            }
            #pragma unroll
            for (int mt = 0; mt < 2; mt++)
                #pragma unroll
                for (int nt = 0; nt < 8; nt++) {
                    asm volatile(
                        "mma.sync.aligned.m16n8k16.row.col.f32.bf16.bf16.f32 "
                        "{%0,%1,%2,%3}, {%4,%5,%6,%7}, {%8,%9}, {%0,%1,%2,%3};"
                        : "+f"(acc[mt][nt][0]), "+f"(acc[mt][nt][1]),
                          "+f"(acc[mt][nt][2]), "+f"(acc[mt][nt][3])
                        : "r"(af[mt][0]), "r"(af[mt][1]), "r"(af[mt][2]), "r"(af[mt][3]),
                          "r"(bf[nt][0]), "r"(bf[nt][1]));
                }
        }
        __syncthreads();
    }

    // ---- epilogue ----
    #pragma unroll
    for (int mt = 0; mt < 2; mt++) {
        const size_t row0 = bm + warp_m + mt * 16 + (lane >> 2);
        #pragma unroll
        for (int nt = 0; nt < 8; nt++) {
            const size_t col = bn + warp_n + nt * 8 + (lane & 3) * 2;
            float bx = 0.f, by = 0.f;
            if (bias) { bx = bias[col]; by = bias[col + 1]; }
            float2 v0 = {acc[mt][nt][0] + bx, acc[mt][nt][1] + by};
            float2 v1 = {acc[mt][nt][2] + bx, acc[mt][nt][3] + by};
            *(float2*)(C + row0 * (size_t)N + col)       = v0;
            *(float2*)(C + (row0 + 8) * (size_t)N + col) = v1;
        }
    }
}

// ---------------------------------------------------------------------------
// Blocked attention (fp32, unchanged). One CTA = one (b,h,g) x 32-query tile.
// ---------------------------------------------------------------------------
constexpr int S_LD  = 513;
constexpr int Q_LD  = 65;
constexpr int KV_LD = 65;
constexpr int ATTN_SMEM = (32 * S_LD + 32 * Q_LD + 64 * KV_LD) * 4;  // 90624 B

__global__ __launch_bounds__(256) void attn_kernel(const float* __restrict__ qkv,
                                                   float* __restrict__ att)
{
    extern __shared__ float sm[];
    float* S   = sm;                    // [32][513]
    float* Qs  = S + 32 * S_LD;         // [32][65]
    float* KVs = Qs + 32 * Q_LD;        // [64][65]

    const int tid = threadIdx.x;
    const int idx = blockIdx.x;
    const int qt  = idx & 15;
    const int bhg = idx >> 4;
    const int g = bhg & 7;
    const int h = (bhg >> 3) & 15;
    const int b = bhg >> 7;

    const int pos0  = g * LG;
    const int qpos0 = pos0 + qt * 32;
    const float scale = 0.125f;

    const float* qbase = qkv + ((size_t)(b * L + qpos0) * (3 * D)) + h * DH;
    const float* kbase = qkv + ((size_t)(b * L + pos0)  * (3 * D)) + D + h * DH;
    const float* vbase = kbase + D;

    #pragma unroll
    for (int i = 0; i < 2; i++) {
        int f = tid + i * 256;
        int row = f >> 4;
        int c4 = (f & 15) * 4;
        float4 v = *(const float4*)(qbase + (size_t)row * (3 * D) + c4);
        float* dst = Qs + row * Q_LD + c4;
        dst[0] = v.x; dst[1] = v.y; dst[2] = v.z; dst[3] = v.w;
    }

    const int lane = tid & 31;
    const int wid  = tid >> 5;
    const int r0 = wid * 4;
    const int c0 = lane * 2;

    // ---- Pass 1: S = scale * Q K^T ----
    for (int ck = 0; ck < 8; ck++) {
        __syncthreads();
        #pragma unroll
        for (int i = 0; i < 4; i++) {
            int f = tid + i * 256;
            int row = f >> 4;
            int c4 = (f & 15) * 4;
            float4 v = *(const float4*)(kbase + (size_t)(ck * 64 + row) * (3 * D) + c4);
            float* dst = KVs + row * KV_LD + c4;
            dst[0] = v.x; dst[1] = v.y; dst[2] = v.z; dst[3] = v.w;
        }
        __syncthreads();

        float acc[4][2] = {};
        #pragma unroll
        for (int d = 0; d < 64; d++) {
            float k0 = KVs[c0 * KV_LD + d];
            float k1 = KVs[(c0 + 1) * KV_LD + d];
            #pragma unroll
            for (int i = 0; i < 4; i++) {
                float q = Qs[(r0 + i) * Q_LD + d];
                acc[i][0] = fmaf(q, k0, acc[i][0]);
                acc[i][1] = fmaf(q, k1, acc[i][1]);
            }
        }
        #pragma unroll
        for (int i = 0; i < 4; i++) {
            S[(r0 + i) * S_LD + ck * 64 + c0]     = acc[i][0] * scale;
            S[(r0 + i) * S_LD + ck * 64 + c0 + 1] = acc[i][1] * scale;
        }
    }
    __syncthreads();

    // ---- Pass 2: row softmax ----
    for (int r = wid * 4; r < wid * 4 + 4; r++) {
        float* row = S + r * S_LD;
        float m = -INFINITY;
        for (int j = lane; j < 512; j += 32) m = fmaxf(m, row[j]);
        #pragma unroll
        for (int o = 16; o; o >>= 1) m = fmaxf(m, __shfl_xor_sync(0xffffffffu, m, o));
        float s = 0.f;
        for (int j = lane; j < 512; j += 32) {
            float e = __expf(row[j] - m);
            row[j] = e;
            s += e;
        }
        #pragma unroll
        for (int o = 16; o; o >>= 1) s += __shfl_xor_sync(0xffffffffu, s, o);
        float inv = 1.0f / s;
        for (int j = lane; j < 512; j += 32) row[j] *= inv;
    }
    __syncthreads();

    // ---- Pass 3: O = P V ----
    float oacc[4][2] = {};
    for (int ck = 0; ck < 8; ck++) {
        __syncthreads();
        #pragma unroll
        for (int i = 0; i < 4; i++) {
            int f = tid + i * 256;
            int row = f >> 4;
            int c4 = (f & 15) * 4;
            float4 v = *(const float4*)(vbase + (size_t)(ck * 64 + row) * (3 * D) + c4);
            float* dst = KVs + row * KV_LD + c4;
            dst[0] = v.x; dst[1] = v.y; dst[2] = v.z; dst[3] = v.w;
        }
        __syncthreads();

        #pragma unroll
        for (int kk = 0; kk < 64; kk++) {
            float v0 = KVs[kk * KV_LD + c0];
            float v1 = KVs[kk * KV_LD + c0 + 1];
            #pragma unroll
            for (int i = 0; i < 4; i++) {
                float p = S[(r0 + i) * S_LD + ck * 64 + kk];
                oacc[i][0] = fmaf(p, v0, oacc[i][0]);
                oacc[i][1] = fmaf(p, v1, oacc[i][1]);
            }
        }
    }

    #pragma unroll
    for (int i = 0; i < 4; i++) {
        float* dst = att + ((size_t)(b * L + qpos0 + r0 + i) * D) + h * DH + c0;
        dst[0] = oacc[i][0];
        dst[1] = oacc[i][1];
    }
}

// ---------------------------------------------------------------------------
extern "C" void kernel_launch(void* const* d_in, const int* in_sizes, int n_in,
                              void* d_out, int out_size)
{
    const float* x     = (const float*)d_in[0];   // [B,L,D]
    const float* w_qkv = (const float*)d_in[1];   // [3D, D]
    const float* w_out = (const float*)d_in[2];   // [D, D]
    const float* b_out = (const float*)d_in[3];   // [D]
    float* out = (float*)d_out;                   // [B,L,D]

    float* qkv_ptr = nullptr;
    float* att_ptr = nullptr;
    __nv_bfloat16 *x2, *att2, *wq2, *wo2;
    cudaGetSymbolAddress((void**)&qkv_ptr, g_qkv);
    cudaGetSymbolAddress((void**)&att_ptr, g_att);
    cudaGetSymbolAddress((void**)&x2,   g_x2);
    cudaGetSymbolAddress((void**)&att2, g_att2);
    cudaGetSymbolAddress((void**)&wq2,  g_wq2);
    cudaGetSymbolAddress((void**)&wo2,  g_wo2);

    cudaFuncSetAttribute(attn_kernel, cudaFuncAttributeMaxDynamicSharedMemorySize,
                         ATTN_SMEM);
    cudaFuncSetAttribute(gemm_mma, cudaFuncAttributeMaxDynamicSharedMemorySize,
                         GEMM_SMEM);

    // Split inputs/weights into bf16 hi/lo K-concatenated operands
    split_fp32_bf16x2<<<M_TOK, 256>>>(x, x2, M_TOK, 0);           // A side
    split_fp32_bf16x2<<<3 * D, 256>>>(w_qkv, wq2, 3 * D, 1);      // B side
    split_fp32_bf16x2<<<D, 256>>>(w_out, wo2, D, 1);              // B side

    // 1) QKV projection on tensor cores: [16384,3072] = x2 @ wq2^T  (K'=3072)
    gemm_mma<<<dim3(3 * D / 128, M_TOK / 128), 256, GEMM_SMEM>>>(
        x2, wq2, nullptr, qkv_ptr, M_TOK, 3 * D, KSPLIT);

    // 2) Blocked attention (fp32)
    attn_kernel<<<Bsz * H * G * 16, 256, ATTN_SMEM>>>(qkv_ptr, att_ptr);

    // Split attention output for GEMM3
    split_fp32_bf16x2<<<M_TOK, 256>>>(att_ptr, att2, M_TOK, 0);   // A side

    // 3) Output projection + bias on tensor cores
    gemm_mma<<<dim3(D / 128, M_TOK / 128), 256, GEMM_SMEM>>>(
        att2, wo2, b_out, out, M_TOK, D, KSPLIT);
}

// round 7
// speedup vs baseline: 2.2521x; 1.2168x over previous
#include <cuda_runtime.h>
#include <cuda_bf16.h>
#include <math.h>
#include <stdint.h>

// Problem constants
constexpr int Bsz = 4;
constexpr int L   = 4096;
constexpr int D   = 1024;
constexpr int H   = 16;
constexpr int G   = 8;
constexpr int LG  = L / G;     // 512
constexpr int DH  = D / H;     // 64
constexpr int M_TOK = Bsz * L; // 16384
constexpr int KSPLIT = 3 * D;  // 3072 : [hi | lo | hi] x [hi | hi | lo]

// Scratch (allocation-free: static __device__ globals)
__device__ float g_qkv[(size_t)M_TOK * 3 * D];            // [B*L, 3D] fp32
__device__ __nv_bfloat16 g_x2  [(size_t)M_TOK * KSPLIT];  // [16384, 3072]
__device__ __nv_bfloat16 g_att2[(size_t)M_TOK * KSPLIT];  // [16384, 3072]
__device__ __nv_bfloat16 g_wq2 [(size_t)(3 * D) * KSPLIT];// [3072, 3072]
__device__ __nv_bfloat16 g_wo2 [(size_t)D * KSPLIT];      // [1024, 3072]

// ---------------------------------------------------------------------------
// helpers
// ---------------------------------------------------------------------------
__device__ __forceinline__ uint32_t swz(uint32_t off) {
    return off ^ ((off >> 3) & 0x70);
}
__device__ __forceinline__ uint32_t s2u(const void* p) {
    uint32_t a;
    asm("{ .reg .u64 t; cvta.to.shared.u64 t, %1; cvt.u32.u64 %0, t; }"
        : "=r"(a) : "l"(p));
    return a;
}
// pack two floats into bf16-hi pair and bf16-lo pair
__device__ __forceinline__ void hilo2(float a, float b, uint32_t& hp, uint32_t& lp) {
    __nv_bfloat16 ha = __float2bfloat16(a);
    __nv_bfloat16 hb = __float2bfloat16(b);
    __nv_bfloat16 la = __float2bfloat16(a - __bfloat162float(ha));
    __nv_bfloat16 lb = __float2bfloat16(b - __bfloat162float(hb));
    hp = (uint32_t)__bfloat16_as_ushort(ha) | ((uint32_t)__bfloat16_as_ushort(hb) << 16);
    lp = (uint32_t)__bfloat16_as_ushort(la) | ((uint32_t)__bfloat16_as_ushort(lb) << 16);
}

#define MMA16816(acc, a, b0, b1)                                             \
    asm volatile(                                                            \
        "mma.sync.aligned.m16n8k16.row.col.f32.bf16.bf16.f32 "               \
        "{%0,%1,%2,%3}, {%4,%5,%6,%7}, {%8,%9}, {%0,%1,%2,%3};"              \
        : "+f"((acc)[0]), "+f"((acc)[1]), "+f"((acc)[2]), "+f"((acc)[3])     \
        : "r"((a)[0]), "r"((a)[1]), "r"((a)[2]), "r"((a)[3]),                \
          "r"(b0), "r"(b1))

#define LDMX4(r, addr)                                                       \
    asm volatile("ldmatrix.sync.aligned.m8n8.x4.shared.b16 {%0,%1,%2,%3}, [%4];" \
        : "=r"((r)[0]), "=r"((r)[1]), "=r"((r)[2]), "=r"((r)[3]) : "r"(addr))

#define LDMX4T(r, addr)                                                      \
    asm volatile("ldmatrix.sync.aligned.m8n8.x4.trans.shared.b16 {%0,%1,%2,%3}, [%4];" \
        : "=r"((r)[0]), "=r"((r)[1]), "=r"((r)[2]), "=r"((r)[3]) : "r"(addr))

// ---------------------------------------------------------------------------
// Split fp32 [rows,1024] -> bf16 [rows,3072].
// mode 0 (A side): [hi | lo | hi]     mode 1 (B side): [hi | hi | lo]
// ---------------------------------------------------------------------------
__global__ void split_fp32_bf16x2(const float* __restrict__ src,
                                  __nv_bfloat16* __restrict__ dst,
                                  int rows, int mode)
{
    int idx = blockIdx.x * 256 + threadIdx.x;
    if (idx >= rows * 256) return;
    int row = idx >> 8;
    int c4  = (idx & 255) << 2;
    float4 v = *(const float4*)(src + (size_t)row * 1024 + c4);
    uint32_t hp0, lp0, hp1, lp1;
    hilo2(v.x, v.y, hp0, lp0);
    hilo2(v.z, v.w, hp1, lp1);
    __nv_bfloat16* base = dst + (size_t)row * KSPLIT + c4;
    if (mode == 0) {
        *(uint32_t*)(base)          = hp0; *(uint32_t*)(base + 2)        = hp1;
        *(uint32_t*)(base + 1024)   = lp0; *(uint32_t*)(base + 1026)     = lp1;
        *(uint32_t*)(base + 2048)   = hp0; *(uint32_t*)(base + 2050)     = hp1;
    } else {
        *(uint32_t*)(base)          = hp0; *(uint32_t*)(base + 2)        = hp1;
        *(uint32_t*)(base + 1024)   = hp0; *(uint32_t*)(base + 1026)     = hp1;
        *(uint32_t*)(base + 2048)   = lp0; *(uint32_t*)(base + 2050)     = lp1;
    }
}

// ---------------------------------------------------------------------------
// mma.sync bf16 NT GEMM (unchanged from R6, passing): C = A*B^T (+bias)
// ---------------------------------------------------------------------------
constexpr int TILE_BYTES = 128 * 128;
constexpr int STAGE_BYTES = 2 * TILE_BYTES;
constexpr int GEMM_SMEM = 3 * STAGE_BYTES;   // 96KB

__global__ __launch_bounds__(256) void gemm_mma(const __nv_bfloat16* __restrict__ A,
                                                const __nv_bfloat16* __restrict__ B,
                                                const float* __restrict__ bias,
                                                float* __restrict__ C,
                                                int M, int N, int Kt)
{
    extern __shared__ __align__(1024) uint8_t smem[];

    const int tid  = threadIdx.x;
    const int wid  = tid >> 5;
    const int lane = tid & 31;
    const int warp_m = (wid & 3) * 32;
    const int warp_n = (wid >> 2) * 64;
    const size_t bm = (size_t)blockIdx.y * 128;
    const size_t bn = (size_t)blockIdx.x * 128;
    const uint32_t sbase = s2u(smem);

    uint32_t soff[4];
    const __nv_bfloat16 *ag[4], *bg[4];
    #pragma unroll
    for (int i = 0; i < 4; i++) {
        int f = tid + i * 256;
        int row = f >> 3;
        int seg = f & 7;
        soff[i] = swz(row * 128 + seg * 16);
        ag[i] = A + (bm + row) * (size_t)Kt + seg * 8;
        bg[i] = B + (bn + row) * (size_t)Kt + seg * 8;
    }

    const int NC = Kt / 64;

    auto issue_copy = [&](int c, int stage) {
        uint32_t sa = sbase + stage * STAGE_BYTES;
        uint32_t sb = sa + TILE_BYTES;
        const int ko = c * 64;
        #pragma unroll
        for (int i = 0; i < 4; i++) {
            asm volatile("cp.async.cg.shared.global [%0], [%1], 16;"
                         :: "r"(sa + soff[i]), "l"(ag[i] + ko));
            asm volatile("cp.async.cg.shared.global [%0], [%1], 16;"
                         :: "r"(sb + soff[i]), "l"(bg[i] + ko));
        }
        asm volatile("cp.async.commit_group;");
    };

    const int a_row = warp_m + (lane & 15);
    const int a_sub = lane >> 4;
    const int b_row = warp_n + ((lane >> 4) & 1) * 8 + (lane & 7);
    const int b_sub = (lane >> 3) & 1;

    float acc[2][8][4];
    #pragma unroll
    for (int mt = 0; mt < 2; mt++)
        #pragma unroll
        for (int nt = 0; nt < 8; nt++)
            #pragma unroll
            for (int q = 0; q < 4; q++) acc[mt][nt][q] = 0.f;

    issue_copy(0, 0);
    if (NC > 1) issue_copy(1, 1);

    for (int c = 0; c < NC; c++) {
        if (c + 2 < NC) {
            issue_copy(c + 2, (c + 2) % 3);
            asm volatile("cp.async.wait_group 2;");
        } else if (c + 1 < NC) {
            asm volatile("cp.async.wait_group 1;");
        } else {
            asm volatile("cp.async.wait_group 0;");
        }
        __syncthreads();

        const uint32_t sa = sbase + (c % 3) * STAGE_BYTES;
        const uint32_t sb = sa + TILE_BYTES;

        #pragma unroll
        for (int kk = 0; kk < 4; kk++) {
            uint32_t af[2][4];
            #pragma unroll
            for (int mt = 0; mt < 2; mt++) {
                uint32_t off = (uint32_t)(a_row + mt * 16) * 128 + kk * 32 + a_sub * 16;
                LDMX4(af[mt], sa + swz(off));
            }
            uint32_t bf[8][2];
            #pragma unroll
            for (int j = 0; j < 4; j++) {
                uint32_t off = (uint32_t)(b_row + j * 16) * 128 + kk * 32 + b_sub * 16;
                uint32_t r[4];
                LDMX4(r, sb + swz(off));
                bf[2 * j][0] = r[0]; bf[2 * j][1] = r[1];
                bf[2 * j + 1][0] = r[2]; bf[2 * j + 1][1] = r[3];
            }
            #pragma unroll
            for (int mt = 0; mt < 2; mt++)
                #pragma unroll
                for (int nt = 0; nt < 8; nt++)
                    MMA16816(acc[mt][nt], af[mt], bf[nt][0], bf[nt][1]);
        }
        __syncthreads();
    }

    #pragma unroll
    for (int mt = 0; mt < 2; mt++) {
        const size_t row0 = bm + warp_m + mt * 16 + (lane >> 2);
        #pragma unroll
        for (int nt = 0; nt < 8; nt++) {
            const size_t col = bn + warp_n + nt * 8 + (lane & 3) * 2;
            float bx = 0.f, by = 0.f;
            if (bias) { bx = bias[col]; by = bias[col + 1]; }
            float2 v0 = {acc[mt][nt][0] + bx, acc[mt][nt][1] + by};
            float2 v1 = {acc[mt][nt][2] + bx, acc[mt][nt][3] + by};
            *(float2*)(C + row0 * (size_t)N + col)       = v0;
            *(float2*)(C + (row0 + 8) * (size_t)N + col) = v1;
        }
    }
}

// ---------------------------------------------------------------------------
// Tensor-core blocked attention with hi/lo bf16 split.
// CTA = one (b,h,g) block x 32 queries; 4 key chunks of 128.
// Phase A: S = Q2*K2^T (K-concat 192) -> regs. Phase B: softmax (cross-warp).
// Phase C: O += P2*V2 per chunk (concat keys 384). Writes g_att2 hi/lo direct.
// ---------------------------------------------------------------------------
// smem byte layout
constexpr int uQ2_OFF = 0;                 // [32][200] bf16  = 12800
constexpr int uK2_OFF = 12800;             // [128][200] bf16 = 51200 (phase A)
constexpr int uV2_OFF = 12800;             // [384][72] bf16  = 55296 (phase C)
constexpr int uP2_OFF = 68096;             // [32][392] bf16  = 25088
constexpr int RED_OFF = 93184;             // 2 x [32][8] float = 2048
constexpr int ATTN_SMEM = 95232;

__global__ __launch_bounds__(256) void attn_tc(const float* __restrict__ qkv,
                                               __nv_bfloat16* __restrict__ att2)
{
    extern __shared__ __align__(16) char smc[];
    const uint32_t sb = s2u(smc);
    float* redM = (float*)(smc + RED_OFF);
    float* redS = redM + 256;

    const int tid  = threadIdx.x;
    const int lane = tid & 31;
    const int wid  = tid >> 5;
    const int q4   = lane >> 2;
    const int kap  = lane & 3;

    const int idx = blockIdx.x;
    const int qt  = idx & 15;
    const int bhg = idx >> 4;
    const int g = bhg & 7;
    const int h = (bhg >> 3) & 15;
    const int b = bhg >> 7;
    const int pos0  = g * LG;
    const int qpos0 = pos0 + qt * 32;

    const float* qptr = qkv + (size_t)(b * L + qpos0) * 3072 + h * 64;
    const float* kptr = qkv + (size_t)(b * L + pos0)  * 3072 + 1024 + h * 64;
    const float* vptr = kptr + 1024;

    // ---- Q2 = [Q_hi | Q_lo | Q_hi], rows stride 200 elems (400 B) ----
    #pragma unroll
    for (int i = 0; i < 2; i++) {
        int f = tid + i * 256;
        int qr = f >> 4;
        int c4 = (f & 15) * 4;
        float4 v = *(const float4*)(qptr + (size_t)qr * 3072 + c4);
        uint32_t hp0, lp0, hp1, lp1;
        hilo2(v.x, v.y, hp0, lp0);
        hilo2(v.z, v.w, hp1, lp1);
        char* base = smc + uQ2_OFF + qr * 400;
        *(uint32_t*)(base + c4 * 2)           = hp0;
        *(uint32_t*)(base + (c4 + 2) * 2)     = hp1;
        *(uint32_t*)(base + (64 + c4) * 2)    = lp0;
        *(uint32_t*)(base + (66 + c4) * 2)    = lp1;
        *(uint32_t*)(base + (128 + c4) * 2)   = hp0;
        *(uint32_t*)(base + (130 + c4) * 2)   = hp1;
    }

    // ---- Phase A: S[c][mt][j][4] over 4 chunks ----
    float sAcc[4][2][2][4];
    #pragma unroll
    for (int c = 0; c < 4; c++)
        #pragma unroll
        for (int mt = 0; mt < 2; mt++)
            #pragma unroll
            for (int j = 0; j < 2; j++)
                #pragma unroll
                for (int r = 0; r < 4; r++) sAcc[c][mt][j][r] = 0.f;

    const int nb = wid * 16;    // warp key strip within chunk
    const int aRowB = (lane & 15);          // + mt*16
    const int aHalf = (lane >> 4) * 8;      // k element offset
    const int bRow  = ((lane >> 4) & 1) * 8 + (lane & 7);
    const int bHalf = ((lane >> 3) & 1) * 8;

    #pragma unroll
    for (int c = 0; c < 4; c++) {
        __syncthreads();  // previous chunk reads done
        // load+convert K chunk -> K2 = [K_hi | K_hi | K_lo]
        #pragma unroll
        for (int i = 0; i < 8; i++) {
            int f = tid + i * 256;
            int kr = f >> 4;
            int c4 = (f & 15) * 4;
            float4 v = *(const float4*)(kptr + (size_t)(c * 128 + kr) * 3072 + c4);
            uint32_t hp0, lp0, hp1, lp1;
            hilo2(v.x, v.y, hp0, lp0);
            hilo2(v.z, v.w, hp1, lp1);
            char* base = smc + uK2_OFF + kr * 400;
            *(uint32_t*)(base + c4 * 2)          = hp0;
            *(uint32_t*)(base + (c4 + 2) * 2)    = hp1;
            *(uint32_t*)(base + (64 + c4) * 2)   = hp0;
            *(uint32_t*)(base + (66 + c4) * 2)   = hp1;
            *(uint32_t*)(base + (128 + c4) * 2)  = lp0;
            *(uint32_t*)(base + (130 + c4) * 2)  = lp1;
        }
        __syncthreads();

        #pragma unroll
        for (int kk = 0; kk < 12; kk++) {
            uint32_t a0[4], a1[4], bq[4];
            LDMX4(a0, sb + uQ2_OFF + (uint32_t)(aRowB)      * 400 + (kk * 16 + aHalf) * 2);
            LDMX4(a1, sb + uQ2_OFF + (uint32_t)(aRowB + 16) * 400 + (kk * 16 + aHalf) * 2);
            LDMX4(bq, sb + uK2_OFF + (uint32_t)(nb + bRow)  * 400 + (kk * 16 + bHalf) * 2);
            MMA16816(sAcc[c][0][0], a0, bq[0], bq[1]);
            MMA16816(sAcc[c][0][1], a0, bq[2], bq[3]);
            MMA16816(sAcc[c][1][0], a1, bq[0], bq[1]);
            MMA16816(sAcc[c][1][1], a1, bq[2], bq[3]);
        }
    }

    // ---- Phase B: softmax over rows (512 cols distributed warp x chunk) ----
    const float scale = 0.125f;
    float rowinv[2][2];
    float rowmax[2][2];

    #pragma unroll
    for (int mt = 0; mt < 2; mt++)
        #pragma unroll
        for (int hh = 0; hh < 2; hh++) {
            float m = -1e30f;
            #pragma unroll
            for (int c = 0; c < 4; c++)
                #pragma unroll
                for (int j = 0; j < 2; j++)
                    m = fmaxf(m, fmaxf(sAcc[c][mt][j][2 * hh], sAcc[c][mt][j][2 * hh + 1]));
            m = fmaxf(m, __shfl_xor_sync(0xffffffffu, m, 1));
            m = fmaxf(m, __shfl_xor_sync(0xffffffffu, m, 2));
            if (kap == 0) redM[(mt * 16 + hh * 8 + q4) * 8 + wid] = m;
        }
    __syncthreads();
    #pragma unroll
    for (int mt = 0; mt < 2; mt++)
        #pragma unroll
        for (int hh = 0; hh < 2; hh++) {
            const int row = mt * 16 + hh * 8 + q4;
            float m = redM[row * 8];
            #pragma unroll
            for (int w = 1; w < 8; w++) m = fmaxf(m, redM[row * 8 + w]);
            rowmax[mt][hh] = m;
            float s = 0.f;
            #pragma unroll
            for (int c = 0; c < 4; c++)
                #pragma unroll
                for (int j = 0; j < 2; j++) {
                    float p0 = __expf((sAcc[c][mt][j][2 * hh]     - m) * scale);
                    float p1 = __expf((sAcc[c][mt][j][2 * hh + 1] - m) * scale);
                    sAcc[c][mt][j][2 * hh]     = p0;
                    sAcc[c][mt][j][2 * hh + 1] = p1;
                    s += p0 + p1;
                }
            s += __shfl_xor_sync(0xffffffffu, s, 1);
            s += __shfl_xor_sync(0xffffffffu, s, 2);
            if (kap == 0) redS[row * 8 + wid] = s;
        }
    __syncthreads();
    #pragma unroll
    for (int mt = 0; mt < 2; mt++)
        #pragma unroll
        for (int hh = 0; hh < 2; hh++) {
            const int row = mt * 16 + hh * 8 + q4;
            float s = redS[row * 8];
            #pragma unroll
            for (int w = 1; w < 8; w++) s += redS[row * 8 + w];
            rowinv[mt][hh] = 1.0f / s;
        }

    // ---- Phase C: O += P2 * V2 per chunk ----
    const int wm = wid & 1;      // m16 tile
    const int wn = wid >> 1;     // n16 strip (0..3) -> dh cols 16*wn
    float oAcc[2][4];
    #pragma unroll
    for (int j = 0; j < 2; j++)
        #pragma unroll
        for (int r = 0; r < 4; r++) oAcc[j][r] = 0.f;

    const int pRowB = (lane & 15);           // + wm*16
    const int pHalf = (lane >> 4) * 8;
    const int vRow  = (lane & 7) + ((lane >> 3) & 1) * 8;   // + kk*16
    const int vCol  = wn * 16 + (lane >> 4) * 8;

    #pragma unroll
    for (int c = 0; c < 4; c++) {
        __syncthreads();  // previous chunk MMAs done before overwrite
        // write P2 chunk = [P_hi | P_lo | P_hi] (unnormalized)
        #pragma unroll
        for (int mt = 0; mt < 2; mt++)
            #pragma unroll
            for (int j = 0; j < 2; j++)
                #pragma unroll
                for (int hh = 0; hh < 2; hh++) {
                    uint32_t hp, lp;
                    hilo2(sAcc[c][mt][j][2 * hh], sAcc[c][mt][j][2 * hh + 1], hp, lp);
                    const int row = mt * 16 + hh * 8 + q4;
                    const int k = wid * 16 + j * 8 + 2 * kap;
                    char* base = smc + uP2_OFF + row * 784;
                    *(uint32_t*)(base + k * 2)         = hp;
                    *(uint32_t*)(base + (128 + k) * 2) = lp;
                    *(uint32_t*)(base + (256 + k) * 2) = hp;
                }
        // load+convert V chunk -> V2 rows [V_hi | V_hi | V_lo] (row = concat key)
        #pragma unroll
        for (int i = 0; i < 8; i++) {
            int f = tid + i * 256;
            int vr = f >> 4;
            int c4 = (f & 15) * 4;
            float4 v = *(const float4*)(vptr + (size_t)(c * 128 + vr) * 3072 + c4);
            uint32_t hp0, lp0, hp1, lp1;
            hilo2(v.x, v.y, hp0, lp0);
            hilo2(v.z, v.w, hp1, lp1);
            char* b0 = smc + uV2_OFF + vr * 144;
            char* b1 = smc + uV2_OFF + (128 + vr) * 144;
            char* b2 = smc + uV2_OFF + (256 + vr) * 144;
            *(uint32_t*)(b0 + c4 * 2)       = hp0;
            *(uint32_t*)(b0 + (c4 + 2) * 2) = hp1;
            *(uint32_t*)(b1 + c4 * 2)       = hp0;
            *(uint32_t*)(b1 + (c4 + 2) * 2) = hp1;
            *(uint32_t*)(b2 + c4 * 2)       = lp0;
            *(uint32_t*)(b2 + (c4 + 2) * 2) = lp1;
        }
        __syncthreads();

        #pragma unroll
        for (int kk = 0; kk < 24; kk++) {
            uint32_t ap[4], bv[4];
            LDMX4(ap, sb + uP2_OFF + (uint32_t)(wm * 16 + pRowB) * 784 + (kk * 16 + pHalf) * 2);
            LDMX4T(bv, sb + uV2_OFF + (uint32_t)(kk * 16 + vRow) * 144 + vCol * 2);
            MMA16816(oAcc[0], ap, bv[0], bv[1]);
            MMA16816(oAcc[1], ap, bv[2], bv[3]);
        }
    }

    // ---- store O directly as hi/lo split into att2 (mode 0) ----
    const float inv0 = rowinv[wm][0];
    const float inv1 = rowinv[wm][1];
    const int r0 = wm * 16 + q4;
    const size_t tr0 = (size_t)(b * L + qpos0 + r0) * 3072 + h * 64;
    const size_t tr1 = tr0 + (size_t)8 * 3072;
    #pragma unroll
    for (int j = 0; j < 2; j++) {
        const int cc = wn * 16 + j * 8 + 2 * kap;
        uint32_t hp, lp;
        hilo2(oAcc[j][0] * inv0, oAcc[j][1] * inv0, hp, lp);
        *(uint32_t*)(att2 + tr0 + cc)        = hp;
        *(uint32_t*)(att2 + tr0 + 1024 + cc) = lp;
        *(uint32_t*)(att2 + tr0 + 2048 + cc) = hp;
        hilo2(oAcc[j][2] * inv1, oAcc[j][3] * inv1, hp, lp);
        *(uint32_t*)(att2 + tr1 + cc)        = hp;
        *(uint32_t*)(att2 + tr1 + 1024 + cc) = lp;
        *(uint32_t*)(att2 + tr1 + 2048 + cc) = hp;
    }
}

// ---------------------------------------------------------------------------
extern "C" void kernel_launch(void* const* d_in, const int* in_sizes, int n_in,
                              void* d_out, int out_size)
{
    const float* x     = (const float*)d_in[0];   // [B,L,D]
    const float* w_qkv = (const float*)d_in[1];   // [3D, D]
    const float* w_out = (const float*)d_in[2];   // [D, D]
    const float* b_out = (const float*)d_in[3];   // [D]
    float* out = (float*)d_out;                   // [B,L,D]

    float* qkv_ptr = nullptr;
    __nv_bfloat16 *x2, *att2, *wq2, *wo2;
    cudaGetSymbolAddress((void**)&qkv_ptr, g_qkv);
    cudaGetSymbolAddress((void**)&x2,   g_x2);
    cudaGetSymbolAddress((void**)&att2, g_att2);
    cudaGetSymbolAddress((void**)&wq2,  g_wq2);
    cudaGetSymbolAddress((void**)&wo2,  g_wo2);

    cudaFuncSetAttribute(gemm_mma, cudaFuncAttributeMaxDynamicSharedMemorySize,
                         GEMM_SMEM);
    cudaFuncSetAttribute(attn_tc, cudaFuncAttributeMaxDynamicSharedMemorySize,
                         ATTN_SMEM);

    // Split inputs/weights into bf16 hi/lo K-concatenated operands
    split_fp32_bf16x2<<<M_TOK, 256>>>(x, x2, M_TOK, 0);           // A side
    split_fp32_bf16x2<<<3 * D, 256>>>(w_qkv, wq2, 3 * D, 1);      // B side
    split_fp32_bf16x2<<<D, 256>>>(w_out, wo2, D, 1);              // B side

    // 1) QKV projection (tensor cores)
    gemm_mma<<<dim3(3 * D / 128, M_TOK / 128), 256, GEMM_SMEM>>>(
        x2, wq2, nullptr, qkv_ptr, M_TOK, 3 * D, KSPLIT);

    // 2) Tensor-core blocked attention -> writes att2 hi/lo directly
    attn_tc<<<Bsz * H * G * 16, 256, ATTN_SMEM>>>(qkv_ptr, att2);

    // 3) Output projection + bias (tensor cores)
    gemm_mma<<<dim3(D / 128, M_TOK / 128), 256, GEMM_SMEM>>>(
        att2, wo2, b_out, out, M_TOK, D, KSPLIT);
}

// round 8
// speedup vs baseline: 2.7599x; 1.2254x over previous
#include <cuda_runtime.h>
#include <cuda_bf16.h>
#include <math.h>
#include <stdint.h>

// Problem constants
constexpr int Bsz = 4;
constexpr int L   = 4096;
constexpr int D   = 1024;
constexpr int H   = 16;
constexpr int G   = 8;
constexpr int LG  = L / G;     // 512
constexpr int DH  = D / H;     // 64
constexpr int M_TOK = Bsz * L; // 16384
constexpr int KSPLIT = 3 * D;  // 3072 : [hi | lo | hi] x [hi | hi | lo]

// Scratch (allocation-free: static __device__ globals)
__device__ __nv_bfloat16 g_qh  [(size_t)M_TOK * 3072];   // qkv hi plane
__device__ __nv_bfloat16 g_ql  [(size_t)M_TOK * 3072];   // qkv lo plane
__device__ __nv_bfloat16 g_x2  [(size_t)M_TOK * KSPLIT];
__device__ __nv_bfloat16 g_att2[(size_t)M_TOK * KSPLIT];
__device__ __nv_bfloat16 g_wq2 [(size_t)(3 * D) * KSPLIT];
__device__ __nv_bfloat16 g_wo2 [(size_t)D * KSPLIT];

// ---------------------------------------------------------------------------
// helpers
// ---------------------------------------------------------------------------
__device__ __forceinline__ uint32_t swz(uint32_t off) {
    return off ^ ((off >> 3) & 0x70);
}
__device__ __forceinline__ uint32_t s2u(const void* p) {
    uint32_t a;
    asm("{ .reg .u64 t; cvta.to.shared.u64 t, %1; cvt.u32.u64 %0, t; }"
        : "=r"(a) : "l"(p));
    return a;
}
__device__ __forceinline__ void hilo2(float a, float b, uint32_t& hp, uint32_t& lp) {
    __nv_bfloat16 ha = __float2bfloat16(a);
    __nv_bfloat16 hb = __float2bfloat16(b);
    __nv_bfloat16 la = __float2bfloat16(a - __bfloat162float(ha));
    __nv_bfloat16 lb = __float2bfloat16(b - __bfloat162float(hb));
    hp = (uint32_t)__bfloat16_as_ushort(ha) | ((uint32_t)__bfloat16_as_ushort(hb) << 16);
    lp = (uint32_t)__bfloat16_as_ushort(la) | ((uint32_t)__bfloat16_as_ushort(lb) << 16);
}

#define MMA16816(acc, a, b0, b1)                                             \
    asm volatile(                                                            \
        "mma.sync.aligned.m16n8k16.row.col.f32.bf16.bf16.f32 "               \
        "{%0,%1,%2,%3}, {%4,%5,%6,%7}, {%8,%9}, {%0,%1,%2,%3};"              \
        : "+f"((acc)[0]), "+f"((acc)[1]), "+f"((acc)[2]), "+f"((acc)[3])     \
        : "r"((a)[0]), "r"((a)[1]), "r"((a)[2]), "r"((a)[3]),                \
          "r"(b0), "r"(b1))

#define LDMX4(r, addr)                                                       \
    asm volatile("ldmatrix.sync.aligned.m8n8.x4.shared.b16 {%0,%1,%2,%3}, [%4];" \
        : "=r"((r)[0]), "=r"((r)[1]), "=r"((r)[2]), "=r"((r)[3]) : "r"(addr))

#define LDMX4T(r, addr)                                                      \
    asm volatile("ldmatrix.sync.aligned.m8n8.x4.trans.shared.b16 {%0,%1,%2,%3}, [%4];" \
        : "=r"((r)[0]), "=r"((r)[1]), "=r"((r)[2]), "=r"((r)[3]) : "r"(addr))

#define CPASYNC16(dst, src)                                                  \
    asm volatile("cp.async.cg.shared.global [%0], [%1], 16;"                 \
        :: "r"(dst), "l"(src))

// ---------------------------------------------------------------------------
// Split fp32 [rows,1024] -> bf16 [rows,3072].
// mode 0 (A side): [hi | lo | hi]     mode 1 (B side): [hi | hi | lo]
// ---------------------------------------------------------------------------
__global__ void split_fp32_bf16x2(const float* __restrict__ src,
                                  __nv_bfloat16* __restrict__ dst,
                                  int rows, int mode)
{
    int idx = blockIdx.x * 256 + threadIdx.x;
    if (idx >= rows * 256) return;
    int row = idx >> 8;
    int c4  = (idx & 255) << 2;
    float4 v = *(const float4*)(src + (size_t)row * 1024 + c4);
    uint32_t hp0, lp0, hp1, lp1;
    hilo2(v.x, v.y, hp0, lp0);
    hilo2(v.z, v.w, hp1, lp1);
    __nv_bfloat16* base = dst + (size_t)row * KSPLIT + c4;
    if (mode == 0) {
        *(uint32_t*)(base)          = hp0; *(uint32_t*)(base + 2)        = hp1;
        *(uint32_t*)(base + 1024)   = lp0; *(uint32_t*)(base + 1026)     = lp1;
        *(uint32_t*)(base + 2048)   = hp0; *(uint32_t*)(base + 2050)     = hp1;
    } else {
        *(uint32_t*)(base)          = hp0; *(uint32_t*)(base + 2)        = hp1;
        *(uint32_t*)(base + 1024)   = hp0; *(uint32_t*)(base + 1026)     = hp1;
        *(uint32_t*)(base + 2048)   = lp0; *(uint32_t*)(base + 2050)     = lp1;
    }
}

// ---------------------------------------------------------------------------
// mma.sync bf16 NT GEMM: C = A*B^T. Output either fp32 (+bias) to C, or
// hi/lo bf16 planes to Ch/Cl (when Ch != nullptr).
// ---------------------------------------------------------------------------
constexpr int TILE_BYTES = 128 * 128;
constexpr int STAGE_BYTES = 2 * TILE_BYTES;
constexpr int GEMM_SMEM = 3 * STAGE_BYTES;   // 96KB

__global__ __launch_bounds__(256) void gemm_mma(const __nv_bfloat16* __restrict__ A,
                                                const __nv_bfloat16* __restrict__ B,
                                                const float* __restrict__ bias,
                                                float* __restrict__ C,
                                                __nv_bfloat16* __restrict__ Ch,
                                                __nv_bfloat16* __restrict__ Cl,
                                                int M, int N, int Kt)
{
    extern __shared__ __align__(1024) uint8_t smem[];

    const int tid  = threadIdx.x;
    const int wid  = tid >> 5;
    const int lane = tid & 31;
    const int warp_m = (wid & 3) * 32;
    const int warp_n = (wid >> 2) * 64;
    const size_t bm = (size_t)blockIdx.y * 128;
    const size_t bn = (size_t)blockIdx.x * 128;
    const uint32_t sbase = s2u(smem);

    uint32_t soff[4];
    const __nv_bfloat16 *ag[4], *bg[4];
    #pragma unroll
    for (int i = 0; i < 4; i++) {
        int f = tid + i * 256;
        int row = f >> 3;
        int seg = f & 7;
        soff[i] = swz(row * 128 + seg * 16);
        ag[i] = A + (bm + row) * (size_t)Kt + seg * 8;
        bg[i] = B + (bn + row) * (size_t)Kt + seg * 8;
    }

    const int NC = Kt / 64;

    auto issue_copy = [&](int c, int stage) {
        uint32_t sa = sbase + stage * STAGE_BYTES;
        uint32_t sb = sa + TILE_BYTES;
        const int ko = c * 64;
        #pragma unroll
        for (int i = 0; i < 4; i++) {
            CPASYNC16(sa + soff[i], ag[i] + ko);
            CPASYNC16(sb + soff[i], bg[i] + ko);
        }
        asm volatile("cp.async.commit_group;");
    };

    const int a_row = warp_m + (lane & 15);
    const int a_sub = lane >> 4;
    const int b_row = warp_n + ((lane >> 4) & 1) * 8 + (lane & 7);
    const int b_sub = (lane >> 3) & 1;

    float acc[2][8][4];
    #pragma unroll
    for (int mt = 0; mt < 2; mt++)
        #pragma unroll
        for (int nt = 0; nt < 8; nt++)
            #pragma unroll
            for (int q = 0; q < 4; q++) acc[mt][nt][q] = 0.f;

    issue_copy(0, 0);
    if (NC > 1) issue_copy(1, 1);

    for (int c = 0; c < NC; c++) {
        if (c + 2 < NC) {
            issue_copy(c + 2, (c + 2) % 3);
            asm volatile("cp.async.wait_group 2;");
        } else if (c + 1 < NC) {
            asm volatile("cp.async.wait_group 1;");
        } else {
            asm volatile("cp.async.wait_group 0;");
        }
        __syncthreads();

        const uint32_t sa = sbase + (c % 3) * STAGE_BYTES;
        const uint32_t sb = sa + TILE_BYTES;

        #pragma unroll
        for (int kk = 0; kk < 4; kk++) {
            uint32_t af[2][4];
            #pragma unroll
            for (int mt = 0; mt < 2; mt++) {
                uint32_t off = (uint32_t)(a_row + mt * 16) * 128 + kk * 32 + a_sub * 16;
                LDMX4(af[mt], sa + swz(off));
            }
            uint32_t bf[8][2];
            #pragma unroll
            for (int j = 0; j < 4; j++) {
                uint32_t off = (uint32_t)(b_row + j * 16) * 128 + kk * 32 + b_sub * 16;
                uint32_t r[4];
                LDMX4(r, sb + swz(off));
                bf[2 * j][0] = r[0]; bf[2 * j][1] = r[1];
                bf[2 * j + 1][0] = r[2]; bf[2 * j + 1][1] = r[3];
            }
            #pragma unroll
            for (int mt = 0; mt < 2; mt++)
                #pragma unroll
                for (int nt = 0; nt < 8; nt++)
                    MMA16816(acc[mt][nt], af[mt], bf[nt][0], bf[nt][1]);
        }
        __syncthreads();
    }

    if (Ch) {
        // split bf16 hi/lo epilogue (for qkv planes)
        #pragma unroll
        for (int mt = 0; mt < 2; mt++) {
            const size_t row0 = bm + warp_m + mt * 16 + (lane >> 2);
            #pragma unroll
            for (int nt = 0; nt < 8; nt++) {
                const size_t col = bn + warp_n + nt * 8 + (lane & 3) * 2;
                uint32_t hp, lp;
                hilo2(acc[mt][nt][0], acc[mt][nt][1], hp, lp);
                *(uint32_t*)(Ch + row0 * (size_t)N + col) = hp;
                *(uint32_t*)(Cl + row0 * (size_t)N + col) = lp;
                hilo2(acc[mt][nt][2], acc[mt][nt][3], hp, lp);
                *(uint32_t*)(Ch + (row0 + 8) * (size_t)N + col) = hp;
                *(uint32_t*)(Cl + (row0 + 8) * (size_t)N + col) = lp;
            }
        }
    } else {
        #pragma unroll
        for (int mt = 0; mt < 2; mt++) {
            const size_t row0 = bm + warp_m + mt * 16 + (lane >> 2);
            #pragma unroll
            for (int nt = 0; nt < 8; nt++) {
                const size_t col = bn + warp_n + nt * 8 + (lane & 3) * 2;
                float bx = 0.f, by = 0.f;
                if (bias) { bx = bias[col]; by = bias[col + 1]; }
                float2 v0 = {acc[mt][nt][0] + bx, acc[mt][nt][1] + by};
                float2 v1 = {acc[mt][nt][2] + bx, acc[mt][nt][3] + by};
                *(float2*)(C + row0 * (size_t)N + col)       = v0;
                *(float2*)(C + (row0 + 8) * (size_t)N + col) = v1;
            }
        }
    }
}

// ---------------------------------------------------------------------------
// Tensor-core blocked attention v2: qkv already in bf16 hi/lo planes.
// CTA = one (b,h,g) x 32 queries. cp.async fills, double-buffered K/V chunks.
// 3-pass accumulation replaces concat duplication:
//   S = Qh*Kh^T + Ql*Kh^T + Qh*Kl^T ;  O = Ph*Vh + Pl*Vh + Ph*Vl.
// ---------------------------------------------------------------------------
constexpr int sQH_OFF  = 0;        // [32][72] bf16  (stride 144B)
constexpr int sQL_OFF  = 4608;
constexpr int sKH0_OFF = 9216;     // [128][72] buf0 hi
constexpr int sKL0_OFF = 27648;    // buf0 lo
constexpr int sKH1_OFF = 46080;    // buf1 hi
constexpr int sKL1_OFF = 64512;    // buf1 lo
constexpr int sPH_OFF  = 82944;    // [32][136] bf16 (stride 272B)
constexpr int sPL_OFF  = 91648;
constexpr int sRED_OFF = 100352;   // 2 x [32][8] float
constexpr int ATTN_SMEM = 102400;  // 100KB -> 2 CTA/SM

__global__ __launch_bounds__(256) void attn_tc(const __nv_bfloat16* __restrict__ qh,
                                               const __nv_bfloat16* __restrict__ ql,
                                               __nv_bfloat16* __restrict__ att2)
{
    extern __shared__ __align__(16) char smc[];
    const uint32_t sbs = s2u(smc);
    float* redM = (float*)(smc + sRED_OFF);
    float* redS = redM + 256;

    const int tid  = threadIdx.x;
    const int lane = tid & 31;
    const int wid  = tid >> 5;
    const int q4   = lane >> 2;
    const int kap  = lane & 3;

    const int idx = blockIdx.x;
    const int qt  = idx & 15;
    const int bhg = idx >> 4;
    const int g = bhg & 7;
    const int h = (bhg >> 3) & 15;
    const int b = bhg >> 7;
    const int pos0  = g * LG;
    const int qpos0 = pos0 + qt * 32;

    const uint32_t kbuf[2][2] = {{sbs + sKH0_OFF, sbs + sKL0_OFF},
                                 {sbs + sKH1_OFF, sbs + sKL1_OFF}};

    // ---- Q fill: 32 rows x 64 cols, 2 planes; 2 cp.async per thread ----
    {
        int row = tid >> 3;
        int seg = tid & 7;
        const size_t go = (size_t)(b * L + qpos0 + row) * 3072 + h * 64 + seg * 8;
        uint32_t so = row * 144 + seg * 16;
        CPASYNC16(sbs + sQH_OFF + so, qh + go);
        CPASYNC16(sbs + sQL_OFF + so, ql + go);
    }

    // K/V chunk loader (plane-split, 8 cp.async per thread)
    auto load_kv = [&](int c, int buf, int colbase) {
        const size_t tok0 = (size_t)(b * L + pos0 + c * 128);
        #pragma unroll
        for (int i = 0; i < 4; i++) {
            int f = tid + i * 256;
            int row = f >> 3;
            int seg = f & 7;
            const size_t go = (tok0 + row) * 3072 + colbase + seg * 8;
            uint32_t so = row * 144 + seg * 16;
            CPASYNC16(kbuf[buf][0] + so, qh + go);
            CPASYNC16(kbuf[buf][1] + so, ql + go);
        }
        asm volatile("cp.async.commit_group;");
    };

    const int kcol = 1024 + h * 64;
    const int vcol = 2048 + h * 64;

    // ---- Phase A: S over 4 key chunks, 3 passes each ----
    float sAcc[4][2][2][4];
    #pragma unroll
    for (int c = 0; c < 4; c++)
        #pragma unroll
        for (int mt = 0; mt < 2; mt++)
            #pragma unroll
            for (int j = 0; j < 2; j++)
                #pragma unroll
                for (int r = 0; r < 4; r++) sAcc[c][mt][j][r] = 0.f;

    const int nb = wid * 16;
    const int aRowB = (lane & 15);
    const int aHalf = (lane >> 4) * 8;
    const int bRow  = ((lane >> 4) & 1) * 8 + (lane & 7);
    const int bHalf = ((lane >> 3) & 1) * 8;

    load_kv(0, 0, kcol);   // group 0 (includes Q cp.asyncs)

    #pragma unroll
    for (int c = 0; c < 4; c++) {
        __syncthreads();                       // prior chunk MMAs done
        if (c + 1 < 4) load_kv(c + 1, (c + 1) & 1, kcol);
        if (c + 1 < 4) { asm volatile("cp.async.wait_group 1;"); }
        else           { asm volatile("cp.async.wait_group 0;"); }
        __syncthreads();

        const uint32_t kh = kbuf[c & 1][0];
        const uint32_t kl = kbuf[c & 1][1];
        const uint32_t qhs = sbs + sQH_OFF;
        const uint32_t qls = sbs + sQL_OFF;

        #pragma unroll
        for (int p = 0; p < 3; p++) {
            const uint32_t qp = (p == 1) ? qls : qhs;
            const uint32_t kp = (p == 2) ? kl  : kh;
            #pragma unroll
            for (int kk = 0; kk < 4; kk++) {
                uint32_t a0[4], a1[4], bq[4];
                LDMX4(a0, qp + (uint32_t)(aRowB)      * 144 + (kk * 16 + aHalf) * 2);
                LDMX4(a1, qp + (uint32_t)(aRowB + 16) * 144 + (kk * 16 + aHalf) * 2);
                LDMX4(bq, kp + (uint32_t)(nb + bRow)  * 144 + (kk * 16 + bHalf) * 2);
                MMA16816(sAcc[c][0][0], a0, bq[0], bq[1]);
                MMA16816(sAcc[c][0][1], a0, bq[2], bq[3]);
                MMA16816(sAcc[c][1][0], a1, bq[0], bq[1]);
                MMA16816(sAcc[c][1][1], a1, bq[2], bq[3]);
            }
        }
    }

    // ---- Phase B: softmax ----
    const float scale = 0.125f;
    float rowinv[2][2];

    #pragma unroll
    for (int mt = 0; mt < 2; mt++)
        #pragma unroll
        for (int hh = 0; hh < 2; hh++) {
            float m = -1e30f;
            #pragma unroll
            for (int c = 0; c < 4; c++)
                #pragma unroll
                for (int j = 0; j < 2; j++)
                    m = fmaxf(m, fmaxf(sAcc[c][mt][j][2 * hh], sAcc[c][mt][j][2 * hh + 1]));
            m = fmaxf(m, __shfl_xor_sync(0xffffffffu, m, 1));
            m = fmaxf(m, __shfl_xor_sync(0xffffffffu, m, 2));
            if (kap == 0) redM[(mt * 16 + hh * 8 + q4) * 8 + wid] = m;
        }
    __syncthreads();
    #pragma unroll
    for (int mt = 0; mt < 2; mt++)
        #pragma unroll
        for (int hh = 0; hh < 2; hh++) {
            const int row = mt * 16 + hh * 8 + q4;
            float m = redM[row * 8];
            #pragma unroll
            for (int w = 1; w < 8; w++) m = fmaxf(m, redM[row * 8 + w]);
            float s = 0.f;
            #pragma unroll
            for (int c = 0; c < 4; c++)
                #pragma unroll
                for (int j = 0; j < 2; j++) {
                    float p0 = __expf((sAcc[c][mt][j][2 * hh]     - m) * scale);
                    float p1 = __expf((sAcc[c][mt][j][2 * hh + 1] - m) * scale);
                    sAcc[c][mt][j][2 * hh]     = p0;
                    sAcc[c][mt][j][2 * hh + 1] = p1;
                    s += p0 + p1;
                }
            s += __shfl_xor_sync(0xffffffffu, s, 1);
            s += __shfl_xor_sync(0xffffffffu, s, 2);
            if (kap == 0) redS[row * 8 + wid] = s;
        }
    __syncthreads();
    #pragma unroll
    for (int mt = 0; mt < 2; mt++)
        #pragma unroll
        for (int hh = 0; hh < 2; hh++) {
            const int row = mt * 16 + hh * 8 + q4;
            float s = redS[row * 8];
            #pragma unroll
            for (int w = 1; w < 8; w++) s += redS[row * 8 + w];
            rowinv[mt][hh] = 1.0f / s;
        }

    // ---- Phase C: O = P*V, 4 chunks, 3 passes ----
    const int wm = wid & 1;
    const int wn = wid >> 1;
    float oAcc[2][4];
    #pragma unroll
    for (int j = 0; j < 2; j++)
        #pragma unroll
        for (int r = 0; r < 4; r++) oAcc[j][r] = 0.f;

    const int pRow = wm * 16 + (lane & 15);
    const int pHalf = (lane >> 4) * 8;
    const int vRow  = (lane & 7) + ((lane >> 3) & 1) * 8;
    const int vCol  = wn * 16 + (lane >> 4) * 8;

    load_kv(0, 0, vcol);    // V chunk 0 (phase A reads fully done: softmax syncs)

    #pragma unroll
    for (int c = 0; c < 4; c++) {
        __syncthreads();                       // prior chunk MMAs + P reads done
        if (c + 1 < 4) load_kv(c + 1, (c + 1) & 1, vcol);

        // write P chunk (hi/lo planes, unnormalized)
        #pragma unroll
        for (int mt = 0; mt < 2; mt++)
            #pragma unroll
            for (int j = 0; j < 2; j++)
                #pragma unroll
                for (int hh = 0; hh < 2; hh++) {
                    uint32_t hp, lp;
                    hilo2(sAcc[c][mt][j][2 * hh], sAcc[c][mt][j][2 * hh + 1], hp, lp);
                    const int row = mt * 16 + hh * 8 + q4;
                    const int k = wid * 16 + j * 8 + 2 * kap;
                    *(uint32_t*)(smc + sPH_OFF + row * 272 + k * 2) = hp;
                    *(uint32_t*)(smc + sPL_OFF + row * 272 + k * 2) = lp;
                }

        if (c + 1 < 4) { asm volatile("cp.async.wait_group 1;"); }
        else           { asm volatile("cp.async.wait_group 0;"); }
        __syncthreads();

        const uint32_t vh = kbuf[c & 1][0];
        const uint32_t vl = kbuf[c & 1][1];
        const uint32_t phs = sbs + sPH_OFF;
        const uint32_t pls = sbs + sPL_OFF;

        #pragma unroll
        for (int p = 0; p < 3; p++) {
            const uint32_t pp = (p == 1) ? pls : phs;
            const uint32_t vp = (p == 2) ? vl  : vh;
            #pragma unroll
            for (int kk = 0; kk < 8; kk++) {
                uint32_t ap[4], bv[4];
                LDMX4(ap, pp + (uint32_t)pRow * 272 + (kk * 16 + pHalf) * 2);
                LDMX4T(bv, vp + (uint32_t)(kk * 16 + vRow) * 144 + vCol * 2);
                MMA16816(oAcc[0], ap, bv[0], bv[1]);
                MMA16816(oAcc[1], ap, bv[2], bv[3]);
            }
        }
    }

    // ---- store O as [hi|lo|hi] split into att2 ----
    const float inv0 = rowinv[wm][0];
    const float inv1 = rowinv[wm][1];
    const int r0 = wm * 16 + q4;
    const size_t tr0 = (size_t)(b * L + qpos0 + r0) * 3072 + h * 64;
    const size_t tr1 = tr0 + (size_t)8 * 3072;
    #pragma unroll
    for (int j = 0; j < 2; j++) {
        const int cc = wn * 16 + j * 8 + 2 * kap;
        uint32_t hp, lp;
        hilo2(oAcc[j][0] * inv0, oAcc[j][1] * inv0, hp, lp);
        *(uint32_t*)(att2 + tr0 + cc)        = hp;
        *(uint32_t*)(att2 + tr0 + 1024 + cc) = lp;
        *(uint32_t*)(att2 + tr0 + 2048 + cc) = hp;
        hilo2(oAcc[j][2] * inv1, oAcc[j][3] * inv1, hp, lp);
        *(uint32_t*)(att2 + tr1 + cc)        = hp;
        *(uint32_t*)(att2 + tr1 + 1024 + cc) = lp;
        *(uint32_t*)(att2 + tr1 + 2048 + cc) = hp;
    }
}

// ---------------------------------------------------------------------------
extern "C" void kernel_launch(void* const* d_in, const int* in_sizes, int n_in,
                              void* d_out, int out_size)
{
    const float* x     = (const float*)d_in[0];
    const float* w_qkv = (const float*)d_in[1];
    const float* w_out = (const float*)d_in[2];
    const float* b_out = (const float*)d_in[3];
    float* out = (float*)d_out;

    __nv_bfloat16 *qhp, *qlp, *x2, *att2, *wq2, *wo2;
    cudaGetSymbolAddress((void**)&qhp,  g_qh);
    cudaGetSymbolAddress((void**)&qlp,  g_ql);
    cudaGetSymbolAddress((void**)&x2,   g_x2);
    cudaGetSymbolAddress((void**)&att2, g_att2);
    cudaGetSymbolAddress((void**)&wq2,  g_wq2);
    cudaGetSymbolAddress((void**)&wo2,  g_wo2);

    cudaFuncSetAttribute(gemm_mma, cudaFuncAttributeMaxDynamicSharedMemorySize,
                         GEMM_SMEM);
    cudaFuncSetAttribute(attn_tc, cudaFuncAttributeMaxDynamicSharedMemorySize,
                         ATTN_SMEM);

    // Split inputs/weights into bf16 hi/lo K-concatenated operands
    split_fp32_bf16x2<<<M_TOK, 256>>>(x, x2, M_TOK, 0);
    split_fp32_bf16x2<<<3 * D, 256>>>(w_qkv, wq2, 3 * D, 1);
    split_fp32_bf16x2<<<D, 256>>>(w_out, wo2, D, 1);

    // 1) QKV projection -> bf16 hi/lo planes directly
    gemm_mma<<<dim3(3 * D / 128, M_TOK / 128), 256, GEMM_SMEM>>>(
        x2, wq2, nullptr, nullptr, qhp, qlp, M_TOK, 3 * D, KSPLIT);

    // 2) Tensor-core blocked attention -> att2 [hi|lo|hi]
    attn_tc<<<Bsz * H * G * 16, 256, ATTN_SMEM>>>(qhp, qlp, att2);

    // 3) Output projection + bias -> fp32 out
    gemm_mma<<<dim3(D / 128, M_TOK / 128), 256, GEMM_SMEM>>>(
        att2, wo2, b_out, out, nullptr, nullptr, M_TOK, D, KSPLIT);
}